// round 1
// baseline (speedup 1.0000x reference)
#include <cuda_runtime.h>
#include <math.h>

// Problem constants
#define E_  8
#define D_  1024
#define F_  4096
#define K_  2
#define T_  8192           // 4 * 2048 tokens
#define TK_ (T_ * K_)      // 16384 routed slots

// ---------------------------------------------------------------------------
// Device scratch (static __device__ arrays -- no allocations allowed)
// ---------------------------------------------------------------------------
__device__ float g_h[(size_t)TK_ * F_];   // 256 MiB: gelu(fc) activations, bucketed by expert
__device__ int   g_tok[E_ * T_];          // token id per (expert, local row)
__device__ float g_wgt[E_ * T_];          // routing weight per (expert, local row)
__device__ int   g_cursor[E_];            // per-expert bucket fill cursor (== count after gate)
__device__ int   g_base[E_];              // prefix sum of counts -> row base in g_h

// ---------------------------------------------------------------------------
// Packed f32x2 helpers (Blackwell FFMA2 path; ptxas will not auto-fuse)
// ---------------------------------------------------------------------------
typedef unsigned long long u64;

__device__ __forceinline__ u64 pk2(float lo, float hi) {
    u64 r; asm("mov.b64 %0, {%1, %2};" : "=l"(r) : "f"(lo), "f"(hi)); return r;
}
__device__ __forceinline__ void upk2(u64 v, float& lo, float& hi) {
    asm("mov.b64 {%0, %1}, %2;" : "=f"(lo), "=f"(hi) : "l"(v));
}
__device__ __forceinline__ void fma2(u64& c, u64 a, u64 b) {
    asm("fma.rn.f32x2 %0, %1, %2, %0;" : "+l"(c) : "l"(a), "l"(b));
}

__device__ __forceinline__ float gelu_tanh(float v) {
    // NewGELU: 0.5*x*(1+tanh(sqrt(2/pi)*(x+0.044715*x^3)))
    float u = 0.7978845608028654f * (v + 0.044715f * v * v * v);
    return 0.5f * v * (1.0f + tanhf(u));
}

// ---------------------------------------------------------------------------
// Kernel 0: reset cursors + zero output (harness poisons d_out each run)
// ---------------------------------------------------------------------------
__global__ void k_zero(float* __restrict__ out, int n_elems) {
    if (blockIdx.x == 0 && threadIdx.x < E_) g_cursor[threadIdx.x] = 0;
    int i = blockIdx.x * blockDim.x + threadIdx.x;
    int stride = gridDim.x * blockDim.x;
    float4 z = make_float4(0.f, 0.f, 0.f, 0.f);
    for (int idx = i; idx * 4 < n_elems; idx += stride)
        reinterpret_cast<float4*>(out)[idx] = z;
}

// ---------------------------------------------------------------------------
// Kernel 1: gating. One warp per token: 8 logits, top-2, softmax, bucket scatter.
// ---------------------------------------------------------------------------
__global__ void k_gate(const float* __restrict__ x, const float* __restrict__ gw) {
    int warp = threadIdx.x >> 5;
    int lane = threadIdx.x & 31;
    int t = blockIdx.x * 8 + warp;
    const float* xr = x + (size_t)t * D_;

    float xv[32];
#pragma unroll
    for (int i = 0; i < 32; i++) xv[i] = xr[i * 32 + lane];

    float logit[E_];
#pragma unroll
    for (int e = 0; e < E_; e++) {
        const float* wr = gw + e * D_;
        float acc = 0.f;
#pragma unroll
        for (int i = 0; i < 32; i++) acc = fmaf(xv[i], wr[i * 32 + lane], acc);
#pragma unroll
        for (int s = 16; s > 0; s >>= 1) acc += __shfl_xor_sync(0xffffffffu, acc, s);
        logit[e] = acc;
    }

    if (lane == 0) {
        // top-2 with first-index tie-break (matches jax.lax.top_k)
        int e0 = 0;
#pragma unroll
        for (int e = 1; e < E_; e++) if (logit[e] > logit[e0]) e0 = e;
        int e1 = (e0 == 0) ? 1 : 0;
#pragma unroll
        for (int e = 0; e < E_; e++) if (e != e0 && logit[e] > logit[e1]) e1 = e;

        float m  = logit[e0];                 // >= logit[e1]
        float x0 = expf(logit[e0] - m);
        float x1 = expf(logit[e1] - m);
        float inv = 1.f / (x0 + x1);

        int p0 = atomicAdd(&g_cursor[e0], 1);
        g_tok[e0 * T_ + p0] = t;  g_wgt[e0 * T_ + p0] = x0 * inv;
        int p1 = atomicAdd(&g_cursor[e1], 1);
        g_tok[e1 * T_ + p1] = t;  g_wgt[e1 * T_ + p1] = x1 * inv;
    }
}

// ---------------------------------------------------------------------------
// Kernel 2: tiny prefix sum of bucket counts -> h row bases
// ---------------------------------------------------------------------------
__global__ void k_prefix() {
    if (threadIdx.x == 0) {
        int b = 0;
        for (int e = 0; e < E_; e++) { g_base[e] = b; b += g_cursor[e]; }
    }
}

// ---------------------------------------------------------------------------
// SGEMM tiling parameters: 128x128 block tile, K-step 16, 256 threads,
// 8x8 micro-tile per thread, packed f32x2 accumulators.
// ---------------------------------------------------------------------------
#define BM 128
#define BN 128
#define BK 16

// Kernel 3: per-expert  H = gelu( gather(X) @ Wfc[e]^T + bfc[e] )
// grid: (F/BN, T/BM, E)
__global__ void __launch_bounds__(256, 2)
k_fc(const float* __restrict__ x, const float* __restrict__ wfc,
     const float* __restrict__ bfc) {
    int e    = blockIdx.z;
    int cnt  = g_cursor[e];
    int row0 = blockIdx.y * BM;
    if (row0 >= cnt) return;
    int n0 = blockIdx.x * BN;

    __shared__ float As[BK][BM];
    __shared__ float Bs[BK][BN];
    __shared__ int   s_off[BM];            // token*D per row (gather offsets)

    int tid = threadIdx.x;
    if (tid < BM) {
        int r = row0 + tid;
        s_off[tid] = (r < cnt ? g_tok[e * T_ + r] : 0) * D_;
    }
    __syncthreads();

    int tx = tid & 15, ty = tid >> 4;
    u64 cc[8][4];
#pragma unroll
    for (int i = 0; i < 8; i++)
#pragma unroll
        for (int j = 0; j < 4; j++) cc[i][j] = 0ull;

    const float* wptr = wfc + (size_t)e * F_ * D_;
    int m0 = tid >> 2,          c0 = (tid & 3) * 4;
    int m1 = (tid + 256) >> 2,  c1 = ((tid + 256) & 3) * 4;

    for (int k0 = 0; k0 < D_; k0 += BK) {
        float4 va0 = *reinterpret_cast<const float4*>(x + s_off[m0] + k0 + c0);
        float4 va1 = *reinterpret_cast<const float4*>(x + s_off[m1] + k0 + c1);
        float4 vb0 = *reinterpret_cast<const float4*>(wptr + (size_t)(n0 + m0) * D_ + k0 + c0);
        float4 vb1 = *reinterpret_cast<const float4*>(wptr + (size_t)(n0 + m1) * D_ + k0 + c1);

        __syncthreads();   // previous tile fully consumed
        As[c0 + 0][m0] = va0.x; As[c0 + 1][m0] = va0.y; As[c0 + 2][m0] = va0.z; As[c0 + 3][m0] = va0.w;
        As[c1 + 0][m1] = va1.x; As[c1 + 1][m1] = va1.y; As[c1 + 2][m1] = va1.z; As[c1 + 3][m1] = va1.w;
        Bs[c0 + 0][m0] = vb0.x; Bs[c0 + 1][m0] = vb0.y; Bs[c0 + 2][m0] = vb0.z; Bs[c0 + 3][m0] = vb0.w;
        Bs[c1 + 0][m1] = vb1.x; Bs[c1 + 1][m1] = vb1.y; Bs[c1 + 2][m1] = vb1.z; Bs[c1 + 3][m1] = vb1.w;
        __syncthreads();   // tile ready

#pragma unroll
        for (int kk = 0; kk < BK; kk++) {
            float4 a0 = *reinterpret_cast<const float4*>(&As[kk][ty * 8]);
            float4 a1 = *reinterpret_cast<const float4*>(&As[kk][ty * 8 + 4]);
            float4 b0 = *reinterpret_cast<const float4*>(&Bs[kk][tx * 8]);
            float4 b1 = *reinterpret_cast<const float4*>(&Bs[kk][tx * 8 + 4]);
            u64 bp0 = pk2(b0.x, b0.y), bp1 = pk2(b0.z, b0.w);
            u64 bp2 = pk2(b1.x, b1.y), bp3 = pk2(b1.z, b1.w);
            float av[8] = {a0.x, a0.y, a0.z, a0.w, a1.x, a1.y, a1.z, a1.w};
#pragma unroll
            for (int i = 0; i < 8; i++) {
                u64 ad = pk2(av[i], av[i]);
                fma2(cc[i][0], ad, bp0);
                fma2(cc[i][1], ad, bp1);
                fma2(cc[i][2], ad, bp2);
                fma2(cc[i][3], ad, bp3);
            }
        }
    }

    // Epilogue: bias + gelu -> g_h (rows bucketed at g_base[e])
    int hbase = g_base[e];
    const float* bf = bfc + e * F_;
#pragma unroll
    for (int i = 0; i < 8; i++) {
        int r = row0 + ty * 8 + i;
        if (r >= cnt) continue;
        float* hrow = g_h + (size_t)(hbase + r) * F_ + n0 + tx * 8;
#pragma unroll
        for (int j = 0; j < 4; j++) {
            float lo, hi; upk2(cc[i][j], lo, hi);
            int col = n0 + tx * 8 + j * 2;
            lo = gelu_tanh(lo + bf[col]);
            hi = gelu_tanh(hi + bf[col + 1]);
            *reinterpret_cast<float2*>(hrow + j * 2) = make_float2(lo, hi);
        }
    }
}

// Kernel 4: per-expert  Y = H @ Wproj[e]^T + bproj[e];  out[token] += w * Y
// grid: (D/BN, T/BM, E)
__global__ void __launch_bounds__(256, 2)
k_proj(const float* __restrict__ wpj, const float* __restrict__ bpj,
       float* __restrict__ out) {
    int e    = blockIdx.z;
    int cnt  = g_cursor[e];
    int row0 = blockIdx.y * BM;
    if (row0 >= cnt) return;
    int n0 = blockIdx.x * BN;
    int hbase = g_base[e];

    __shared__ float As[BK][BM];
    __shared__ float Bs[BK][BN];

    int tid = threadIdx.x;
    int tx = tid & 15, ty = tid >> 4;
    u64 cc[8][4];
#pragma unroll
    for (int i = 0; i < 8; i++)
#pragma unroll
        for (int j = 0; j < 4; j++) cc[i][j] = 0ull;

    const float* wptr = wpj + (size_t)e * D_ * F_;
    const float* aptr = g_h + (size_t)hbase * F_;
    int m0 = tid >> 2,          c0 = (tid & 3) * 4;
    int m1 = (tid + 256) >> 2,  c1 = ((tid + 256) & 3) * 4;
    // clamp gather rows so out-of-bucket tiles read valid memory (results masked)
    int ar0 = min(row0 + m0, cnt - 1);
    int ar1 = min(row0 + m1, cnt - 1);

    for (int k0 = 0; k0 < F_; k0 += BK) {
        float4 va0 = *reinterpret_cast<const float4*>(aptr + (size_t)ar0 * F_ + k0 + c0);
        float4 va1 = *reinterpret_cast<const float4*>(aptr + (size_t)ar1 * F_ + k0 + c1);
        float4 vb0 = *reinterpret_cast<const float4*>(wptr + (size_t)(n0 + m0) * F_ + k0 + c0);
        float4 vb1 = *reinterpret_cast<const float4*>(wptr + (size_t)(n0 + m1) * F_ + k0 + c1);

        __syncthreads();
        As[c0 + 0][m0] = va0.x; As[c0 + 1][m0] = va0.y; As[c0 + 2][m0] = va0.z; As[c0 + 3][m0] = va0.w;
        As[c1 + 0][m1] = va1.x; As[c1 + 1][m1] = va1.y; As[c1 + 2][m1] = va1.z; As[c1 + 3][m1] = va1.w;
        Bs[c0 + 0][m0] = vb0.x; Bs[c0 + 1][m0] = vb0.y; Bs[c0 + 2][m0] = vb0.z; Bs[c0 + 3][m0] = vb0.w;
        Bs[c1 + 0][m1] = vb1.x; Bs[c1 + 1][m1] = vb1.y; Bs[c1 + 2][m1] = vb1.z; Bs[c1 + 3][m1] = vb1.w;
        __syncthreads();

#pragma unroll
        for (int kk = 0; kk < BK; kk++) {
            float4 a0 = *reinterpret_cast<const float4*>(&As[kk][ty * 8]);
            float4 a1 = *reinterpret_cast<const float4*>(&As[kk][ty * 8 + 4]);
            float4 b0 = *reinterpret_cast<const float4*>(&Bs[kk][tx * 8]);
            float4 b1 = *reinterpret_cast<const float4*>(&Bs[kk][tx * 8 + 4]);
            u64 bp0 = pk2(b0.x, b0.y), bp1 = pk2(b0.z, b0.w);
            u64 bp2 = pk2(b1.x, b1.y), bp3 = pk2(b1.z, b1.w);
            float av[8] = {a0.x, a0.y, a0.z, a0.w, a1.x, a1.y, a1.z, a1.w};
#pragma unroll
            for (int i = 0; i < 8; i++) {
                u64 ad = pk2(av[i], av[i]);
                fma2(cc[i][0], ad, bp0);
                fma2(cc[i][1], ad, bp1);
                fma2(cc[i][2], ad, bp2);
                fma2(cc[i][3], ad, bp3);
            }
        }
    }

    // Epilogue: (acc + bias) * routing_weight, atomic scatter-add to out.
    // Exactly two commutative float adds land on each out element -> deterministic.
    const float* bp = bpj + e * D_;
#pragma unroll
    for (int i = 0; i < 8; i++) {
        int r = row0 + ty * 8 + i;
        if (r >= cnt) continue;
        int   token = g_tok[e * T_ + r];
        float w     = g_wgt[e * T_ + r];
        float* orow = out + (size_t)token * D_ + n0 + tx * 8;
#pragma unroll
        for (int j = 0; j < 4; j++) {
            float lo, hi; upk2(cc[i][j], lo, hi);
            int col = n0 + tx * 8 + j * 2;
            atomicAdd(orow + j * 2,     (lo + bp[col])     * w);
            atomicAdd(orow + j * 2 + 1, (hi + bp[col + 1]) * w);
        }
    }
}

// ---------------------------------------------------------------------------
// Launch: zero -> gate -> prefix -> fc+gelu -> proj+scatter (all graph-safe)
// ---------------------------------------------------------------------------
extern "C" void kernel_launch(void* const* d_in, const int* in_sizes, int n_in,
                              void* d_out, int out_size) {
    const float* x   = (const float*)d_in[0];  // [4,2048,1024]
    const float* gw  = (const float*)d_in[1];  // [8,1024]
    const float* wfc = (const float*)d_in[2];  // [8,4096,1024]
    const float* bfc = (const float*)d_in[3];  // [8,4096]
    const float* wpj = (const float*)d_in[4];  // [8,1024,4096]
    const float* bpj = (const float*)d_in[5];  // [8,1024]
    float* out = (float*)d_out;                // [4,2048,1024] fp32

    k_zero  <<<2048, 256>>>(out, out_size);
    k_gate  <<<T_ / 8, 256>>>(x, gw);
    k_prefix<<<1, 32>>>();
    k_fc    <<<dim3(F_ / BN, T_ / BM, E_), 256>>>(x, wfc, bfc);
    k_proj  <<<dim3(D_ / BN, T_ / BM, E_), 256>>>(wpj, bpj, out);
}

// round 5
// speedup vs baseline: 2.9637x; 2.9637x over previous
#include <cuda_runtime.h>
#include <cuda_bf16.h>
#include <math.h>
#include <stdint.h>

// Problem constants
#define E_  8
#define D_  1024
#define F_  4096
#define T_  8192
#define TK_ (T_ * 2)

// GEMM tiling
#define BM 128
#define BN 128
#define KC 64                  // K elements per chunk (128B bf16 rows, SW128)
#define NTH 256
#define TILE_B 16384           // 128 rows x 128B
#define AH_OFF 0
#define AL_OFF 16384
#define BH_OFF 32768
#define BL_OFF 49152
#define BUF_B  65536
#define SMEM_DYN (2 * BUF_B)   // 128 KB double-buffered

// ---------------------------------------------------------------------------
// Device scratch (static: no allocations allowed)
// ---------------------------------------------------------------------------
__device__ __nv_bfloat16 g_xh[(size_t)T_ * D_];
__device__ __nv_bfloat16 g_xl[(size_t)T_ * D_];
__device__ __nv_bfloat16 g_wfh[(size_t)E_ * F_ * D_];
__device__ __nv_bfloat16 g_wfl[(size_t)E_ * F_ * D_];
__device__ __nv_bfloat16 g_wph[(size_t)E_ * D_ * F_];
__device__ __nv_bfloat16 g_wpl[(size_t)E_ * D_ * F_];
__device__ __nv_bfloat16 g_hh[(size_t)TK_ * F_];
__device__ __nv_bfloat16 g_hl[(size_t)TK_ * F_];
__device__ int   g_tok[E_ * T_];
__device__ float g_wgt[E_ * T_];
__device__ int   g_cursor[E_];
__device__ int   g_base[E_];

// ---------------------------------------------------------------------------
// Helpers
// ---------------------------------------------------------------------------
static __device__ __forceinline__ uint32_t smem_u32(const void* p) {
    uint32_t a;
    asm("{ .reg .u64 t; cvta.to.shared.u64 t, %1; cvt.u32.u64 %0, t; }"
        : "=r"(a) : "l"(p));
    return a;
}

#define SW(o) ((o) ^ (((o) >> 3) & 0x70))

#define CPA(dst, src) \
    asm volatile("cp.async.cg.shared.global [%0], [%1], 16;" \
                 :: "r"(dst), "l"(src) : "memory")
#define CPA_COMMIT() asm volatile("cp.async.commit_group;" ::: "memory")

#define LDSM4(r, addr) \
    asm volatile("ldmatrix.sync.aligned.m8n8.x4.shared.b16 {%0,%1,%2,%3}, [%4];" \
                 : "=r"((r)[0]), "=r"((r)[1]), "=r"((r)[2]), "=r"((r)[3]) \
                 : "r"(addr))

#define MMA(cd, a, b0, b1) \
    asm volatile("mma.sync.aligned.m16n8k16.row.col.f32.bf16.bf16.f32 " \
                 "{%0,%1,%2,%3}, {%4,%5,%6,%7}, {%8,%9}, {%0,%1,%2,%3};" \
                 : "+f"((cd)[0]), "+f"((cd)[1]), "+f"((cd)[2]), "+f"((cd)[3]) \
                 : "r"((a)[0]), "r"((a)[1]), "r"((a)[2]), "r"((a)[3]), \
                   "r"(b0), "r"(b1))

static __device__ __forceinline__ float ngelu(float v) {
    float u = 0.7978845608028654f * (v + 0.044715f * v * v * v);
    return 0.5f * v * (1.0f + tanhf(u));
}

// One K=64 chunk of the 3-term split MMA. Fully unrolled.
// Terms: Ah*Bh + Ah*Bl + Al*Bh (Al*Bl dropped, ~2^-18 relative).
static __device__ __forceinline__ void mma_chunk(
    uint32_t bufb, int warp_m, int warp_n,
    int rA, int bA, int rB, int bB, float (&c)[4][4][4]) {
#pragma unroll
    for (int ks = 0; ks < 4; ks++) {
        int kb = ks * 32;
        uint32_t Af[4][4], Bh[2][4], Bl[2][4];
#pragma unroll
        for (int f = 0; f < 4; f++) {
            uint32_t off = (uint32_t)((warp_m * 64 + f * 16 + rA) * 128 + kb + bA);
            LDSM4(Af[f], bufb + AH_OFF + SW(off));
        }
#pragma unroll
        for (int p = 0; p < 2; p++) {
            uint32_t off = (uint32_t)((warp_n * 32 + p * 16 + rB) * 128 + kb + bB);
            LDSM4(Bh[p], bufb + BH_OFF + SW(off));
        }
#pragma unroll
        for (int p = 0; p < 2; p++) {
            uint32_t off = (uint32_t)((warp_n * 32 + p * 16 + rB) * 128 + kb + bB);
            LDSM4(Bl[p], bufb + BL_OFF + SW(off));
        }
#pragma unroll
        for (int f = 0; f < 4; f++)
#pragma unroll
            for (int nf = 0; nf < 4; nf++)
                MMA(c[f][nf], Af[f], Bh[nf >> 1][(nf & 1) * 2], Bh[nf >> 1][(nf & 1) * 2 + 1]);
#pragma unroll
        for (int f = 0; f < 4; f++)
#pragma unroll
            for (int nf = 0; nf < 4; nf++)
                MMA(c[f][nf], Af[f], Bl[nf >> 1][(nf & 1) * 2], Bl[nf >> 1][(nf & 1) * 2 + 1]);
        // reload A with the lo part (reuses Af registers)
#pragma unroll
        for (int f = 0; f < 4; f++) {
            uint32_t off = (uint32_t)((warp_m * 64 + f * 16 + rA) * 128 + kb + bA);
            LDSM4(Af[f], bufb + AL_OFF + SW(off));
        }
#pragma unroll
        for (int f = 0; f < 4; f++)
#pragma unroll
            for (int nf = 0; nf < 4; nf++)
                MMA(c[f][nf], Af[f], Bh[nf >> 1][(nf & 1) * 2], Bh[nf >> 1][(nf & 1) * 2 + 1]);
    }
}

// ---------------------------------------------------------------------------
// Kernel 0: reset cursors + zero output
// ---------------------------------------------------------------------------
__global__ void k_zero(float* __restrict__ out, int n_elems) {
    if (blockIdx.x == 0 && threadIdx.x < E_) g_cursor[threadIdx.x] = 0;
    int i = blockIdx.x * blockDim.x + threadIdx.x;
    int stride = gridDim.x * blockDim.x;
    float4 z = make_float4(0.f, 0.f, 0.f, 0.f);
    for (int idx = i; idx * 4 < n_elems; idx += stride)
        reinterpret_cast<float4*>(out)[idx] = z;
}

// ---------------------------------------------------------------------------
// Kernel 1: fp32 -> bf16 hi/lo split (grid-stride over float4)
// ---------------------------------------------------------------------------
__global__ void k_split(const float4* __restrict__ src,
                        uint2* __restrict__ hi, uint2* __restrict__ lo, int n4) {
    int i = blockIdx.x * blockDim.x + threadIdx.x;
    int stride = gridDim.x * blockDim.x;
    for (int idx = i; idx < n4; idx += stride) {
        float4 v = src[idx];
        __nv_bfloat16 hx = __float2bfloat16(v.x), hy = __float2bfloat16(v.y);
        __nv_bfloat16 hz = __float2bfloat16(v.z), hw = __float2bfloat16(v.w);
        float lx = v.x - __bfloat162float(hx), ly = v.y - __bfloat162float(hy);
        float lz = v.z - __bfloat162float(hz), lw = v.w - __bfloat162float(hw);
        uint2 H, L;
        H.x = ((uint32_t)__bfloat16_as_ushort(hy) << 16) | __bfloat16_as_ushort(hx);
        H.y = ((uint32_t)__bfloat16_as_ushort(hw) << 16) | __bfloat16_as_ushort(hz);
        __nv_bfloat16 ax = __float2bfloat16(lx), ay = __float2bfloat16(ly);
        __nv_bfloat16 az = __float2bfloat16(lz), aw = __float2bfloat16(lw);
        L.x = ((uint32_t)__bfloat16_as_ushort(ay) << 16) | __bfloat16_as_ushort(ax);
        L.y = ((uint32_t)__bfloat16_as_ushort(aw) << 16) | __bfloat16_as_ushort(az);
        hi[idx] = H;
        lo[idx] = L;
    }
}

// ---------------------------------------------------------------------------
// Kernel 2: gating (one warp per token)
// ---------------------------------------------------------------------------
__global__ void k_gate(const float* __restrict__ x, const float* __restrict__ gw) {
    int warp = threadIdx.x >> 5;
    int lane = threadIdx.x & 31;
    int t = blockIdx.x * 8 + warp;
    const float* xr = x + (size_t)t * D_;

    float xv[32];
#pragma unroll
    for (int i = 0; i < 32; i++) xv[i] = xr[i * 32 + lane];

    float logit[E_];
#pragma unroll
    for (int e = 0; e < E_; e++) {
        const float* wr = gw + e * D_;
        float acc = 0.f;
#pragma unroll
        for (int i = 0; i < 32; i++) acc = fmaf(xv[i], wr[i * 32 + lane], acc);
#pragma unroll
        for (int s = 16; s > 0; s >>= 1) acc += __shfl_xor_sync(0xffffffffu, acc, s);
        logit[e] = acc;
    }

    if (lane == 0) {
        int e0 = 0;
#pragma unroll
        for (int e = 1; e < E_; e++) if (logit[e] > logit[e0]) e0 = e;
        int e1 = (e0 == 0) ? 1 : 0;
#pragma unroll
        for (int e = 0; e < E_; e++) if (e != e0 && logit[e] > logit[e1]) e1 = e;

        float m  = logit[e0];
        float x0 = expf(logit[e0] - m);
        float x1 = expf(logit[e1] - m);
        float inv = 1.f / (x0 + x1);

        int p0 = atomicAdd(&g_cursor[e0], 1);
        g_tok[e0 * T_ + p0] = t;  g_wgt[e0 * T_ + p0] = x0 * inv;
        int p1 = atomicAdd(&g_cursor[e1], 1);
        g_tok[e1 * T_ + p1] = t;  g_wgt[e1 * T_ + p1] = x1 * inv;
    }
}

__global__ void k_prefix() {
    if (threadIdx.x == 0) {
        int b = 0;
        for (int e = 0; e < E_; e++) { g_base[e] = b; b += g_cursor[e]; }
    }
}

// ---------------------------------------------------------------------------
// Kernel 3: GEMM1  H = gelu(gather(X) @ Wfc[e]^T + b)  (bf16 HMMA, 3-term)
// grid (F/128, T/128, E), 256 threads
// ---------------------------------------------------------------------------
__global__ void __launch_bounds__(NTH, 1)
k_fc_mma(const float* __restrict__ bfc) {
    int e = blockIdx.z;
    int cnt = g_cursor[e];
    int row0 = blockIdx.y * BM;
    if (row0 >= cnt) return;
    int n0 = blockIdx.x * BN;

    extern __shared__ __align__(1024) char smem[];
    __shared__ int s_toff[BM];
    int tid = threadIdx.x, wid = tid >> 5, lane = tid & 31;
    uint32_t sb = smem_u32(smem);

    if (tid < BM) s_toff[tid] = g_tok[e * T_ + min(row0 + tid, cnt - 1)] * D_;
    __syncthreads();

    int warp_m = wid >> 2, warp_n = wid & 3;
    int g = lane >> 3, l8 = lane & 7;
    int rA = (g & 1) * 8 + l8, bA = (g >> 1) * 16;
    int rB = (g >> 1) * 8 + l8, bB = (g & 1) * 16;

    int ur[4], uc[4];
#pragma unroll
    for (int j = 0; j < 4; j++) { int u = tid + j * NTH; ur[j] = u >> 3; uc[j] = u & 7; }

    const __nv_bfloat16* wh = g_wfh + (size_t)e * F_ * D_;
    const __nv_bfloat16* wl = g_wfl + (size_t)e * F_ * D_;

    // prefetch chunk 0
    {
        uint32_t bufb = sb;
#pragma unroll
        for (int j = 0; j < 4; j++) {
            uint32_t dst = SW((uint32_t)(ur[j] * 128 + uc[j] * 16));
            size_t ao = (size_t)s_toff[ur[j]] + uc[j] * 8;
            size_t bo = (size_t)(n0 + ur[j]) * D_ + uc[j] * 8;
            CPA(bufb + AH_OFF + dst, g_xh + ao);
            CPA(bufb + AL_OFF + dst, g_xl + ao);
            CPA(bufb + BH_OFF + dst, wh + bo);
            CPA(bufb + BL_OFF + dst, wl + bo);
        }
        CPA_COMMIT();
    }

    float c[4][4][4];
#pragma unroll
    for (int f = 0; f < 4; f++)
#pragma unroll
        for (int nf = 0; nf < 4; nf++)
#pragma unroll
            for (int q = 0; q < 4; q++) c[f][nf][q] = 0.f;

    const int KCH = D_ / KC;   // 16
    for (int i = 0; i < KCH; i++) {
        if (i + 1 < KCH) {
            uint32_t bufb = sb + ((i + 1) & 1) * BUF_B;
            int k0 = (i + 1) * KC;
#pragma unroll
            for (int j = 0; j < 4; j++) {
                uint32_t dst = SW((uint32_t)(ur[j] * 128 + uc[j] * 16));
                size_t ao = (size_t)s_toff[ur[j]] + k0 + uc[j] * 8;
                size_t bo = (size_t)(n0 + ur[j]) * D_ + k0 + uc[j] * 8;
                CPA(bufb + AH_OFF + dst, g_xh + ao);
                CPA(bufb + AL_OFF + dst, g_xl + ao);
                CPA(bufb + BH_OFF + dst, wh + bo);
                CPA(bufb + BL_OFF + dst, wl + bo);
            }
            CPA_COMMIT();
            asm volatile("cp.async.wait_group 1;" ::: "memory");
        } else {
            asm volatile("cp.async.wait_group 0;" ::: "memory");
        }
        __syncthreads();
        mma_chunk(sb + (i & 1) * BUF_B, warp_m, warp_n, rA, bA, rB, bB, c);
        __syncthreads();
    }

    // Epilogue: bias + gelu -> split bf16 hi/lo into g_hh/g_hl
    int qr = lane >> 2, qc = (lane & 3) * 2;
    int hbase = g_base[e];
#pragma unroll
    for (int f = 0; f < 4; f++) {
#pragma unroll
        for (int pr = 0; pr < 2; pr++) {
            int r = row0 + warp_m * 64 + f * 16 + qr + pr * 8;
            if (r >= cnt) continue;
            size_t hr = (size_t)(hbase + r);
#pragma unroll
            for (int nf = 0; nf < 4; nf++) {
                int n = n0 + warp_n * 32 + nf * 8 + qc;
                float v0 = ngelu(c[f][nf][pr * 2 + 0] + bfc[e * F_ + n]);
                float v1 = ngelu(c[f][nf][pr * 2 + 1] + bfc[e * F_ + n + 1]);
                __nv_bfloat16 h0 = __float2bfloat16(v0), h1 = __float2bfloat16(v1);
                float l0 = v0 - __bfloat162float(h0), l1 = v1 - __bfloat162float(h1);
                __nv_bfloat16 a0 = __float2bfloat16(l0), a1 = __float2bfloat16(l1);
                *reinterpret_cast<uint32_t*>(g_hh + hr * F_ + n) =
                    ((uint32_t)__bfloat16_as_ushort(h1) << 16) | __bfloat16_as_ushort(h0);
                *reinterpret_cast<uint32_t*>(g_hl + hr * F_ + n) =
                    ((uint32_t)__bfloat16_as_ushort(a1) << 16) | __bfloat16_as_ushort(a0);
            }
        }
    }
}

// ---------------------------------------------------------------------------
// Kernel 4: GEMM2  out[token] += w * (H @ Wproj[e]^T + b)
// grid (D/128, T/128, E)
// ---------------------------------------------------------------------------
__global__ void __launch_bounds__(NTH, 1)
k_proj_mma(const float* __restrict__ bpj, float* __restrict__ out) {
    int e = blockIdx.z;
    int cnt = g_cursor[e];
    int row0 = blockIdx.y * BM;
    if (row0 >= cnt) return;
    int n0 = blockIdx.x * BN;

    extern __shared__ __align__(1024) char smem[];
    __shared__ int   s_hrow[BM];
    __shared__ int   s_tok[BM];
    __shared__ float s_wgt[BM];
    int tid = threadIdx.x, wid = tid >> 5, lane = tid & 31;
    uint32_t sb = smem_u32(smem);

    if (tid < BM) {
        int r = min(row0 + tid, cnt - 1);
        s_hrow[tid] = g_base[e] + r;
        s_tok[tid]  = g_tok[e * T_ + r];
        s_wgt[tid]  = g_wgt[e * T_ + r];
    }
    __syncthreads();

    int warp_m = wid >> 2, warp_n = wid & 3;
    int g = lane >> 3, l8 = lane & 7;
    int rA = (g & 1) * 8 + l8, bA = (g >> 1) * 16;
    int rB = (g >> 1) * 8 + l8, bB = (g & 1) * 16;

    int ur[4], uc[4];
#pragma unroll
    for (int j = 0; j < 4; j++) { int u = tid + j * NTH; ur[j] = u >> 3; uc[j] = u & 7; }

    const __nv_bfloat16* wh = g_wph + (size_t)e * D_ * F_;
    const __nv_bfloat16* wl = g_wpl + (size_t)e * D_ * F_;

    {
        uint32_t bufb = sb;
#pragma unroll
        for (int j = 0; j < 4; j++) {
            uint32_t dst = SW((uint32_t)(ur[j] * 128 + uc[j] * 16));
            size_t ao = (size_t)s_hrow[ur[j]] * F_ + uc[j] * 8;
            size_t bo = (size_t)(n0 + ur[j]) * F_ + uc[j] * 8;
            CPA(bufb + AH_OFF + dst, g_hh + ao);
            CPA(bufb + AL_OFF + dst, g_hl + ao);
            CPA(bufb + BH_OFF + dst, wh + bo);
            CPA(bufb + BL_OFF + dst, wl + bo);
        }
        CPA_COMMIT();
    }

    float c[4][4][4];
#pragma unroll
    for (int f = 0; f < 4; f++)
#pragma unroll
        for (int nf = 0; nf < 4; nf++)
#pragma unroll
            for (int q = 0; q < 4; q++) c[f][nf][q] = 0.f;

    const int KCH = F_ / KC;   // 64
    for (int i = 0; i < KCH; i++) {
        if (i + 1 < KCH) {
            uint32_t bufb = sb + ((i + 1) & 1) * BUF_B;
            int k0 = (i + 1) * KC;
#pragma unroll
            for (int j = 0; j < 4; j++) {
                uint32_t dst = SW((uint32_t)(ur[j] * 128 + uc[j] * 16));
                size_t ao = (size_t)s_hrow[ur[j]] * F_ + k0 + uc[j] * 8;
                size_t bo = (size_t)(n0 + ur[j]) * F_ + k0 + uc[j] * 8;
                CPA(bufb + AH_OFF + dst, g_hh + ao);
                CPA(bufb + AL_OFF + dst, g_hl + ao);
                CPA(bufb + BH_OFF + dst, wh + bo);
                CPA(bufb + BL_OFF + dst, wl + bo);
            }
            CPA_COMMIT();
            asm volatile("cp.async.wait_group 1;" ::: "memory");
        } else {
            asm volatile("cp.async.wait_group 0;" ::: "memory");
        }
        __syncthreads();
        mma_chunk(sb + (i & 1) * BUF_B, warp_m, warp_n, rA, bA, rB, bB, c);
        __syncthreads();
    }

    // Epilogue: (acc + bias) * routing weight, atomic scatter (2 adds/elem total)
    int qr = lane >> 2, qc = (lane & 3) * 2;
#pragma unroll
    for (int f = 0; f < 4; f++) {
#pragma unroll
        for (int pr = 0; pr < 2; pr++) {
            int rl = warp_m * 64 + f * 16 + qr + pr * 8;
            int r = row0 + rl;
            if (r >= cnt) continue;
            int   token = s_tok[rl];
            float w     = s_wgt[rl];
            float* orow = out + (size_t)token * D_;
#pragma unroll
            for (int nf = 0; nf < 4; nf++) {
                int n = n0 + warp_n * 32 + nf * 8 + qc;
                atomicAdd(orow + n,     (c[f][nf][pr * 2 + 0] + bpj[e * D_ + n])     * w);
                atomicAdd(orow + n + 1, (c[f][nf][pr * 2 + 1] + bpj[e * D_ + n + 1]) * w);
            }
        }
    }
}

// ---------------------------------------------------------------------------
// Launch
// ---------------------------------------------------------------------------
extern "C" void kernel_launch(void* const* d_in, const int* in_sizes, int n_in,
                              void* d_out, int out_size) {
    const float* x   = (const float*)d_in[0];
    const float* gw  = (const float*)d_in[1];
    const float* wfc = (const float*)d_in[2];
    const float* bfc = (const float*)d_in[3];
    const float* wpj = (const float*)d_in[4];
    const float* bpj = (const float*)d_in[5];
    float* out = (float*)d_out;

    cudaFuncSetAttribute(k_fc_mma,   cudaFuncAttributeMaxDynamicSharedMemorySize, SMEM_DYN);
    cudaFuncSetAttribute(k_proj_mma, cudaFuncAttributeMaxDynamicSharedMemorySize, SMEM_DYN);

    __nv_bfloat16 *xh, *xl, *wfh, *wfl, *wph, *wpl;
    cudaGetSymbolAddress((void**)&xh,  g_xh);
    cudaGetSymbolAddress((void**)&xl,  g_xl);
    cudaGetSymbolAddress((void**)&wfh, g_wfh);
    cudaGetSymbolAddress((void**)&wfl, g_wfl);
    cudaGetSymbolAddress((void**)&wph, g_wph);
    cudaGetSymbolAddress((void**)&wpl, g_wpl);

    k_zero  <<<2048, 256>>>(out, out_size);
    k_gate  <<<T_ / 8, 256>>>(x, gw);
    k_prefix<<<1, 32>>>();
    k_split <<<2048, 256>>>((const float4*)x,   (uint2*)xh,  (uint2*)xl,  T_ * D_ / 4);
    k_split <<<4096, 256>>>((const float4*)wfc, (uint2*)wfh, (uint2*)wfl, E_ * F_ * D_ / 4);
    k_split <<<4096, 256>>>((const float4*)wpj, (uint2*)wph, (uint2*)wpl, E_ * D_ * F_ / 4);
    k_fc_mma  <<<dim3(F_ / BN, T_ / BM, E_), NTH, SMEM_DYN>>>(bfc);
    k_proj_mma<<<dim3(D_ / BN, T_ / BM, E_), NTH, SMEM_DYN>>>(bpj, out);
}